// round 3
// baseline (speedup 1.0000x reference)
#include <cuda_runtime.h>
#include <mma.h>
#include <math.h>
#include <stdint.h>

using namespace nvcuda;

// ---------------- problem constants ----------------
constexpr int kB = 2, kS = 2048, kT = kB * kS;  // 4096 tokens
constexpr int kD = 768, kE = 4, kL = 2, kH = 3072;
constexpr float kEPS = 1e-6f;

// ---------------- GEMM tiling ----------------
constexpr int BM = 128, BN = 128, BK = 32;
constexpr int MAXROWS = kT + kE * BM;   // 4608 (each expert segment padded to BM)
constexpr int NT_MAX  = MAXROWS / BM;   // 36 row tiles max
constexpr int LDA_S = BK + 4;           // 36
constexpr int LDB_S = BN + 4;           // 132
constexpr int LDC_S = 20;

// ---------------- device scratch (no allocs allowed) ----------------
__device__ float g_xbuf[(size_t)kT * kD];            // running residual x
__device__ float g_hbuf[(size_t)kT * kD];            // layernorm output
__device__ float g_abuf[(size_t)MAXROWS * kH];       // GEMM1+gelu output (padded-row space)
__device__ int   g_perm[MAXROWS];                    // padded-row -> token (-1 = pad)
__device__ int   g_cnt[kE];
__device__ int   g_fill[kE];
__device__ int   g_off[kE + 1];

// ---------------- routing ----------------
__global__ void route_init() {
    int t = blockIdx.x * blockDim.x + threadIdx.x;
    if (t < kE) { g_cnt[t] = 0; g_fill[t] = 0; }
    if (t < MAXROWS) g_perm[t] = -1;
}

__global__ void route_count(const int* __restrict__ eix) {
    int t = blockIdx.x * blockDim.x + threadIdx.x;
    if (t < kT) atomicAdd(&g_cnt[eix[t]], 1);
}

__global__ void route_offsets() {
    if (threadIdx.x == 0) {
        int o = 0;
        g_off[0] = 0;
        for (int e = 0; e < kE; e++) {
            o += ((g_cnt[e] + BM - 1) / BM) * BM;
            g_off[e + 1] = o;
        }
    }
}

__global__ void route_scatter(const int* __restrict__ eix) {
    int t = blockIdx.x * blockDim.x + threadIdx.x;
    if (t < kT) {
        int e = eix[t];
        int p = g_off[e] + atomicAdd(&g_fill[e], 1);
        g_perm[p] = t;
    }
}

// ---------------- copy x -> x_buf ----------------
__global__ void copy_x(const float4* __restrict__ src) {
    int i = blockIdx.x * blockDim.x + threadIdx.x;
    reinterpret_cast<float4*>(g_xbuf)[i] = src[i];
}

// ---------------- layernorm ----------------
__device__ __forceinline__ float block_sum(float v) {
    __shared__ float sh[8];
    int lane = threadIdx.x & 31;
    int w = threadIdx.x >> 5;
#pragma unroll
    for (int o = 16; o > 0; o >>= 1) v += __shfl_xor_sync(0xffffffffu, v, o);
    __syncthreads();
    if (lane == 0) sh[w] = v;
    __syncthreads();
    float r = sh[lane & 7];
#pragma unroll
    for (int o = 4; o > 0; o >>= 1) r += __shfl_xor_sync(0xffffffffu, r, o);
    return r;
}

__global__ void ln_kernel(const float* __restrict__ lng, const float* __restrict__ lnb) {
    int tok = blockIdx.x;
    const float* xr = g_xbuf + (size_t)tok * kD;
    int t = threadIdx.x;
    float v0 = xr[t], v1 = xr[t + 256], v2 = xr[t + 512];
    float mu = block_sum(v0 + v1 + v2) * (1.0f / kD);
    float d0 = v0 - mu, d1 = v1 - mu, d2 = v2 - mu;
    float var = block_sum(d0 * d0 + d1 * d1 + d2 * d2) * (1.0f / kD);
    float rs = rsqrtf(var + kEPS);
    float* hr = g_hbuf + (size_t)tok * kD;
    hr[t]       = d0 * rs * lng[t]       + lnb[t];
    hr[t + 256] = d1 * rs * lng[t + 256] + lnb[t + 256];
    hr[t + 512] = d2 * rs * lng[t + 512] + lnb[t + 512];
}

// ---------------- grouped GEMM (tf32 WMMA) ----------------
// FIRST=true:  A = gathered LN output (g_hbuf via g_perm), C = gelu(A*W1+b1) -> g_abuf
// FIRST=false: A = g_abuf (padded rows), C scattered: out[tok] = g_xbuf[tok] + A*W2+b2
template <bool FIRST>
__global__ void __launch_bounds__(256) gemm_kernel(
    const float* __restrict__ W,     // [E, Kdim, Ndim] for this layer
    const float* __restrict__ bias,  // [E, Ndim]
    float* __restrict__ dout,        // only for !FIRST: external out, or nullptr -> g_xbuf
    int Kdim, int Ndim)
{
    __shared__ float As[BM * LDA_S];
    __shared__ float Bs[BK * LDB_S];
    __shared__ int   row_tok[BM];
    __shared__ float cstage[8][16 * LDC_S];

    const int tile = blockIdx.y;
    const int n0 = blockIdx.x * BN;
    const int total = g_off[kE];
    if (tile * BM >= total) return;

    // which expert owns this row tile
    int e = 0;
#pragma unroll
    for (int i = 1; i <= kE; i++)
        if (tile * BM >= g_off[i]) e = i;
    // e is now largest i with off[i] <= tile*BM, and tile*BM < off[e+1]

    const int tid = threadIdx.x;
    if (tid < BM) row_tok[tid] = g_perm[tile * BM + tid];
    __syncthreads();

    const float* Wp = W + (size_t)e * Kdim * Ndim;
    const float* bp = bias + (size_t)e * Ndim;

    const int wid = tid >> 5;
    const int lane = tid & 31;
    const int wr = wid >> 1;  // 0..3 -> rows [wr*32, wr*32+32)
    const int wc = wid & 1;   // 0..1 -> cols [wc*64, wc*64+64)

    wmma::fragment<wmma::accumulator, 16, 16, 8, float> acc[2][4];
#pragma unroll
    for (int i = 0; i < 2; i++)
#pragma unroll
        for (int j = 0; j < 4; j++) wmma::fill_fragment(acc[i][j], 0.0f);

    for (int k0 = 0; k0 < Kdim; k0 += BK) {
        // --- load A tile (128 x 32) ---
#pragma unroll
        for (int j = 0; j < 4; j++) {
            int idx = tid + j * 256;
            int r = idx >> 3, c4 = idx & 7;
            float4 v;
            if (FIRST) {
                int tok = row_tok[r];
                if (tok >= 0)
                    v = *reinterpret_cast<const float4*>(g_hbuf + (size_t)tok * kD + k0 + c4 * 4);
                else
                    v = make_float4(0.f, 0.f, 0.f, 0.f);
            } else {
                v = *reinterpret_cast<const float4*>(
                        g_abuf + (size_t)(tile * BM + r) * kH + k0 + c4 * 4);
            }
            *reinterpret_cast<float4*>(&As[r * LDA_S + c4 * 4]) = v;
        }
        // --- load B tile (32 x 128) ---
#pragma unroll
        for (int j = 0; j < 4; j++) {
            int idx = tid + j * 256;
            int r = idx >> 5, c4 = idx & 31;
            float4 v = *reinterpret_cast<const float4*>(
                Wp + (size_t)(k0 + r) * Ndim + n0 + c4 * 4);
            *reinterpret_cast<float4*>(&Bs[r * LDB_S + c4 * 4]) = v;
        }
        __syncthreads();

#pragma unroll
        for (int ks = 0; ks < BK / 8; ks++) {
            wmma::fragment<wmma::matrix_a, 16, 16, 8, wmma::precision::tf32, wmma::row_major> af[2];
            wmma::fragment<wmma::matrix_b, 16, 16, 8, wmma::precision::tf32, wmma::row_major> bf[4];
#pragma unroll
            for (int i = 0; i < 2; i++) {
                wmma::load_matrix_sync(af[i], &As[(wr * 32 + i * 16) * LDA_S + ks * 8], LDA_S);
#pragma unroll
                for (int t = 0; t < af[i].num_elements; t++)
                    af[i].x[t] = wmma::__float_to_tf32(af[i].x[t]);
            }
#pragma unroll
            for (int jf = 0; jf < 4; jf++) {
                wmma::load_matrix_sync(bf[jf], &Bs[(ks * 8) * LDB_S + wc * 64 + jf * 16], LDB_S);
#pragma unroll
                for (int t = 0; t < bf[jf].num_elements; t++)
                    bf[jf].x[t] = wmma::__float_to_tf32(bf[jf].x[t]);
            }
#pragma unroll
            for (int i = 0; i < 2; i++)
#pragma unroll
                for (int jf = 0; jf < 4; jf++)
                    wmma::mma_sync(acc[i][jf], af[i], bf[jf], acc[i][jf]);
        }
        __syncthreads();
    }

    // --- epilogue ---
    float* outp = nullptr;
    if (!FIRST) outp = dout ? dout : g_xbuf;

#pragma unroll
    for (int i = 0; i < 2; i++) {
#pragma unroll
        for (int jf = 0; jf < 4; jf++) {
            wmma::store_matrix_sync(&cstage[wid][0], acc[i][jf], LDC_S, wmma::mem_row_major);
            __syncwarp();
            int r0 = wr * 32 + i * 16;
            int c0 = n0 + wc * 64 + jf * 16;
#pragma unroll
            for (int t = 0; t < 8; t++) {
                int lin = t * 32 + lane;  // coalesced: 16 consecutive cols per half-warp
                int lr = lin >> 4, lc = lin & 15;
                float val = cstage[wid][lr * LDC_S + lc] + bp[c0 + lc];
                if (FIRST) {
                    float gv = 0.5f * val * (1.0f + erff(val * 0.70710678118654752f));
                    g_abuf[(size_t)(tile * BM + r0 + lr) * kH + c0 + lc] = gv;
                } else {
                    int tok = row_tok[r0 + lr];
                    if (tok >= 0) {
                        size_t o = (size_t)tok * kD + c0 + lc;
                        outp[o] = g_xbuf[o] + val;
                    }
                }
            }
            __syncwarp();
        }
    }
}

// ---------------- launch ----------------
extern "C" void kernel_launch(void* const* d_in, const int* in_sizes, int n_in,
                              void* d_out, int out_size) {
    const float* x   = (const float*)d_in[0];
    const int*   eix = (const int*)d_in[1];
    const float* W1  = (const float*)d_in[2];
    const float* b1  = (const float*)d_in[3];
    const float* W2  = (const float*)d_in[4];
    const float* b2  = (const float*)d_in[5];
    const float* lng = (const float*)d_in[6];
    const float* lnb = (const float*)d_in[7];
    float* out = (float*)d_out;

    copy_x<<<(kT * kD / 4) / 256, 256>>>((const float4*)x);
    route_init<<<(MAXROWS + 255) / 256, 256>>>();
    route_count<<<kT / 256, 256>>>(eix);
    route_offsets<<<1, 32>>>();
    route_scatter<<<kT / 256, 256>>>(eix);

    for (int l = 0; l < kL; l++) {
        ln_kernel<<<kT, 256>>>(lng + (size_t)l * kD, lnb + (size_t)l * kD);
        gemm_kernel<true><<<dim3(kH / BN, NT_MAX), 256>>>(
            W1 + (size_t)l * kE * kD * kH,
            b1 + (size_t)l * kE * kH,
            nullptr, kD, kH);
        gemm_kernel<false><<<dim3(kD / BN, NT_MAX), 256>>>(
            W2 + (size_t)l * kE * kH * kD,
            b2 + (size_t)l * kE * kD,
            (l == kL - 1) ? out : nullptr, kH, kD);
    }
}

// round 4
// speedup vs baseline: 1.2703x; 1.2703x over previous
#include <cuda_runtime.h>
#include <mma.h>
#include <math.h>
#include <stdint.h>

using namespace nvcuda;

// ---------------- problem constants ----------------
constexpr int kB = 2, kS = 2048, kT = kB * kS;  // 4096 tokens
constexpr int kD = 768, kE = 4, kL = 2, kH = 3072;
constexpr float kEPS = 1e-6f;

// ---------------- GEMM tiling ----------------
constexpr int BM = 128, BN = 128, BK = 32;
constexpr int MAXROWS = kT + kE * BM;   // 4608 (each expert segment padded to BM)
constexpr int NT_MAX  = MAXROWS / BM;   // 36 row tiles max
constexpr int LDA_S = BK + 4;           // 36 floats (144B, 16B-aligned rows)
constexpr int LDB_S = BN + 4;           // 132 floats (528B, 16B-aligned rows)
constexpr int LDC_S = 20;

constexpr int A_BUF_ELEMS = BM * LDA_S;             // 4608
constexpr int B_BUF_ELEMS = BK * LDB_S;             // 4224
constexpr int SMEM_FLOATS = 2 * A_BUF_ELEMS + 2 * B_BUF_ELEMS;  // 17664
constexpr int SMEM_BYTES  = SMEM_FLOATS * 4;        // 70656

// ---------------- device scratch (no allocs allowed) ----------------
__device__ float g_xbuf[(size_t)kT * kD];            // running residual x
__device__ float g_hbuf[(size_t)kT * kD];            // layernorm output
__device__ float g_abuf[(size_t)MAXROWS * kH];       // GEMM1+gelu output (padded-row space)
__device__ int   g_perm[MAXROWS];                    // padded-row -> token (-1 = pad)
__device__ int   g_cnt[kE];
__device__ int   g_fill[kE];
__device__ int   g_off[kE + 1];

// ---------------- cp.async helpers ----------------
__device__ __forceinline__ void cp_async16(float* smem, const float* gmem, int src_bytes) {
    uint32_t s = (uint32_t)__cvta_generic_to_shared(smem);
    asm volatile("cp.async.cg.shared.global [%0], [%1], 16, %2;\n"
                 :: "r"(s), "l"(gmem), "r"(src_bytes));
}
__device__ __forceinline__ void cp_commit() {
    asm volatile("cp.async.commit_group;\n");
}
template <int N>
__device__ __forceinline__ void cp_wait() {
    asm volatile("cp.async.wait_group %0;\n" :: "n"(N));
}

// ---------------- routing ----------------
__global__ void route_init() {
    int t = blockIdx.x * blockDim.x + threadIdx.x;
    if (t < kE) { g_cnt[t] = 0; g_fill[t] = 0; }
    if (t < MAXROWS) g_perm[t] = -1;
}

__global__ void route_count(const int* __restrict__ eix) {
    int t = blockIdx.x * blockDim.x + threadIdx.x;
    if (t < kT) atomicAdd(&g_cnt[eix[t]], 1);
}

__global__ void route_offsets() {
    if (threadIdx.x == 0) {
        int o = 0;
        g_off[0] = 0;
        for (int e = 0; e < kE; e++) {
            o += ((g_cnt[e] + BM - 1) / BM) * BM;
            g_off[e + 1] = o;
        }
    }
}

__global__ void route_scatter(const int* __restrict__ eix) {
    int t = blockIdx.x * blockDim.x + threadIdx.x;
    if (t < kT) {
        int e = eix[t];
        int p = g_off[e] + atomicAdd(&g_fill[e], 1);
        g_perm[p] = t;
    }
}

// ---------------- copy x -> x_buf ----------------
__global__ void copy_x(const float4* __restrict__ src) {
    int i = blockIdx.x * blockDim.x + threadIdx.x;
    reinterpret_cast<float4*>(g_xbuf)[i] = src[i];
}

// ---------------- layernorm ----------------
__device__ __forceinline__ float block_sum(float v) {
    __shared__ float sh[8];
    int lane = threadIdx.x & 31;
    int w = threadIdx.x >> 5;
#pragma unroll
    for (int o = 16; o > 0; o >>= 1) v += __shfl_xor_sync(0xffffffffu, v, o);
    __syncthreads();
    if (lane == 0) sh[w] = v;
    __syncthreads();
    float r = sh[lane & 7];
#pragma unroll
    for (int o = 4; o > 0; o >>= 1) r += __shfl_xor_sync(0xffffffffu, r, o);
    return r;
}

__global__ void ln_kernel(const float* __restrict__ lng, const float* __restrict__ lnb) {
    int tok = blockIdx.x;
    const float* xr = g_xbuf + (size_t)tok * kD;
    int t = threadIdx.x;
    float v0 = xr[t], v1 = xr[t + 256], v2 = xr[t + 512];
    float mu = block_sum(v0 + v1 + v2) * (1.0f / kD);
    float d0 = v0 - mu, d1 = v1 - mu, d2 = v2 - mu;
    float var = block_sum(d0 * d0 + d1 * d1 + d2 * d2) * (1.0f / kD);
    float rs = rsqrtf(var + kEPS);
    float* hr = g_hbuf + (size_t)tok * kD;
    hr[t]       = d0 * rs * lng[t]       + lnb[t];
    hr[t + 256] = d1 * rs * lng[t + 256] + lnb[t + 256];
    hr[t + 512] = d2 * rs * lng[t + 512] + lnb[t + 512];
}

// ---------------- grouped GEMM (tf32 WMMA, 2-stage cp.async pipeline) ----------------
// FIRST=true:  A = gathered LN output (g_hbuf via g_perm), C = gelu(A*W1+b1) -> g_abuf
// FIRST=false: A = g_abuf (padded rows), C scattered: out[tok] = g_xbuf[tok] + A*W2+b2
template <bool FIRST>
__global__ void __launch_bounds__(256) gemm_kernel(
    const float* __restrict__ W,     // [E, Kdim, Ndim] for this layer
    const float* __restrict__ bias,  // [E, Ndim]
    float* __restrict__ dout,        // only for !FIRST: external out, or nullptr -> g_xbuf
    int Kdim, int Ndim)
{
    extern __shared__ float dyns[];
    float* As = dyns;                         // [2][A_BUF_ELEMS]
    float* Bs = dyns + 2 * A_BUF_ELEMS;       // [2][B_BUF_ELEMS]
    // epilogue staging aliases the (dead) A buffers: 8 warps * 16*LDC_S floats
    float* cstage = dyns;

    __shared__ int row_tok[BM];

    const int tile = blockIdx.y;
    const int n0 = blockIdx.x * BN;
    const int total = g_off[kE];
    if (tile * BM >= total) return;

    // which expert owns this row tile
    int e = 0;
#pragma unroll
    for (int i = 1; i <= kE; i++)
        if (tile * BM >= g_off[i]) e = i;

    const int tid = threadIdx.x;
    if (tid < BM) row_tok[tid] = g_perm[tile * BM + tid];
    __syncthreads();

    const float* Wp = W + (size_t)e * Kdim * Ndim;
    const float* bp = bias + (size_t)e * Ndim;

    const int wid = tid >> 5;
    const int lane = tid & 31;
    const int wr = wid >> 1;  // 0..3 -> rows [wr*32, wr*32+32)
    const int wc = wid & 1;   // 0..1 -> cols [wc*64, wc*64+64)

    // per-thread load coordinates (fixed across iterations)
    const int ar = tid >> 3, ac4 = tid & 7;      // A: 128 rows x 8 chunks (w/ j stride 256 -> 4 rows ea? no: idx pattern below)
    const int br = tid >> 5, bc4 = tid & 31;     // B: 8 rows per j-step

    auto load_tile = [&](int k0, int buf) {
        float* Ab = As + buf * A_BUF_ELEMS;
        float* Bb = Bs + buf * B_BUF_ELEMS;
        // --- A tile (128 x 32), 4 chunks of 256 threads * 16B ---
#pragma unroll
        for (int j = 0; j < 4; j++) {
            int idx = tid + j * 256;
            int r = idx >> 3, c4 = idx & 7;
            if (FIRST) {
                int tok = row_tok[r];
                const float* src = g_hbuf + (size_t)(tok < 0 ? 0 : tok) * kD + k0 + c4 * 4;
                cp_async16(&Ab[r * LDA_S + c4 * 4], src, tok >= 0 ? 16 : 0);
            } else {
                cp_async16(&Ab[r * LDA_S + c4 * 4],
                           g_abuf + (size_t)(tile * BM + r) * kH + k0 + c4 * 4, 16);
            }
        }
        // --- B tile (32 x 128) ---
#pragma unroll
        for (int j = 0; j < 4; j++) {
            int idx = tid + j * 256;
            int r = idx >> 5, c4 = idx & 31;
            cp_async16(&Bb[r * LDB_S + c4 * 4],
                       Wp + (size_t)(k0 + r) * Ndim + n0 + c4 * 4, 16);
        }
        cp_commit();
    };

    wmma::fragment<wmma::accumulator, 16, 16, 8, float> acc[2][4];
#pragma unroll
    for (int i = 0; i < 2; i++)
#pragma unroll
        for (int j = 0; j < 4; j++) wmma::fill_fragment(acc[i][j], 0.0f);

    const int KT = Kdim / BK;
    load_tile(0, 0);

    for (int it = 0; it < KT; ++it) {
        const int cur = it & 1;
        if (it + 1 < KT) {
            load_tile((it + 1) * BK, (it + 1) & 1);
            cp_wait<1>();
        } else {
            cp_wait<0>();
        }
        __syncthreads();

        const float* Ab = As + cur * A_BUF_ELEMS;
        const float* Bb = Bs + cur * B_BUF_ELEMS;
#pragma unroll
        for (int ks = 0; ks < BK / 8; ks++) {
            wmma::fragment<wmma::matrix_a, 16, 16, 8, wmma::precision::tf32, wmma::row_major> af[2];
            wmma::fragment<wmma::matrix_b, 16, 16, 8, wmma::precision::tf32, wmma::row_major> bf[4];
#pragma unroll
            for (int i = 0; i < 2; i++) {
                wmma::load_matrix_sync(af[i], &Ab[(wr * 32 + i * 16) * LDA_S + ks * 8], LDA_S);
#pragma unroll
                for (int t = 0; t < af[i].num_elements; t++)
                    af[i].x[t] = wmma::__float_to_tf32(af[i].x[t]);
            }
#pragma unroll
            for (int jf = 0; jf < 4; jf++) {
                wmma::load_matrix_sync(bf[jf], &Bb[(ks * 8) * LDB_S + wc * 64 + jf * 16], LDB_S);
#pragma unroll
                for (int t = 0; t < bf[jf].num_elements; t++)
                    bf[jf].x[t] = wmma::__float_to_tf32(bf[jf].x[t]);
            }
#pragma unroll
            for (int i = 0; i < 2; i++)
#pragma unroll
                for (int jf = 0; jf < 4; jf++)
                    wmma::mma_sync(acc[i][jf], af[i], bf[jf], acc[i][jf]);
        }
        __syncthreads();
    }

    // --- epilogue (cstage aliases As; mainloop done, smem sync'd above) ---
    float* outp = nullptr;
    if (!FIRST) outp = dout ? dout : g_xbuf;
    float* cw = cstage + wid * (16 * LDC_S);

#pragma unroll
    for (int i = 0; i < 2; i++) {
#pragma unroll
        for (int jf = 0; jf < 4; jf++) {
            wmma::store_matrix_sync(cw, acc[i][jf], LDC_S, wmma::mem_row_major);
            __syncwarp();
            int r0 = wr * 32 + i * 16;
            int c0 = n0 + wc * 64 + jf * 16;
#pragma unroll
            for (int t = 0; t < 8; t++) {
                int lin = t * 32 + lane;  // coalesced: 16 consecutive cols per half-warp
                int lr = lin >> 4, lc = lin & 15;
                float val = cw[lr * LDC_S + lc] + bp[c0 + lc];
                if (FIRST) {
                    float gv = 0.5f * val * (1.0f + erff(val * 0.70710678118654752f));
                    g_abuf[(size_t)(tile * BM + r0 + lr) * kH + c0 + lc] = gv;
                } else {
                    int tok = row_tok[r0 + lr];
                    if (tok >= 0) {
                        size_t o = (size_t)tok * kD + c0 + lc;
                        outp[o] = g_xbuf[o] + val;
                    }
                }
            }
            __syncwarp();
        }
    }
}

// ---------------- launch ----------------
extern "C" void kernel_launch(void* const* d_in, const int* in_sizes, int n_in,
                              void* d_out, int out_size) {
    const float* x   = (const float*)d_in[0];
    const int*   eix = (const int*)d_in[1];
    const float* W1  = (const float*)d_in[2];
    const float* b1  = (const float*)d_in[3];
    const float* W2  = (const float*)d_in[4];
    const float* b2  = (const float*)d_in[5];
    const float* lng = (const float*)d_in[6];
    const float* lnb = (const float*)d_in[7];
    float* out = (float*)d_out;

    // opt-in to >48KB dynamic smem (immediate API, not a stream op; capture-safe)
    cudaFuncSetAttribute(gemm_kernel<true>,
                         cudaFuncAttributeMaxDynamicSharedMemorySize, SMEM_BYTES);
    cudaFuncSetAttribute(gemm_kernel<false>,
                         cudaFuncAttributeMaxDynamicSharedMemorySize, SMEM_BYTES);

    copy_x<<<(kT * kD / 4) / 256, 256>>>((const float4*)x);
    route_init<<<(MAXROWS + 255) / 256, 256>>>();
    route_count<<<kT / 256, 256>>>(eix);
    route_offsets<<<1, 32>>>();
    route_scatter<<<kT / 256, 256>>>(eix);

    for (int l = 0; l < kL; l++) {
        ln_kernel<<<kT, 256>>>(lng + (size_t)l * kD, lnb + (size_t)l * kD);
        gemm_kernel<true><<<dim3(kH / BN, NT_MAX), 256, SMEM_BYTES>>>(
            W1 + (size_t)l * kE * kD * kH,
            b1 + (size_t)l * kE * kH,
            nullptr, kD, kH);
        gemm_kernel<false><<<dim3(kD / BN, NT_MAX), 256, SMEM_BYTES>>>(
            W2 + (size_t)l * kE * kH * kD,
            b2 + (size_t)l * kE * kD,
            (l == kL - 1) ? out : nullptr, kH, kD);
    }
}